// round 9
// baseline (speedup 1.0000x reference)
#include <cuda_runtime.h>

// Row-normalize: out[row, :] = adj[row, :] * inv(sum(adj[row, :]))
// adj: [L*B*N, N] fp32, N = 2048. One CTA per row.
// sm_103a 256-bit global accesses: each thread does exactly ONE
// ld.global.v8.f32 (32 B) and ONE st.global.v8.f32 — minimal LSU
// wavefronts for the 512 MiB stream.

static constexpr int ROW_N   = 2048;
static constexpr int THREADS = 256;          // 8 floats per thread = one v8
static constexpr int NWARPS  = THREADS / 32;

__device__ __forceinline__ void ldg_v8_cs(const float* p, float* r) {
    asm volatile(
        "ld.global.cs.v8.f32 {%0,%1,%2,%3,%4,%5,%6,%7}, [%8];"
        : "=f"(r[0]), "=f"(r[1]), "=f"(r[2]), "=f"(r[3]),
          "=f"(r[4]), "=f"(r[5]), "=f"(r[6]), "=f"(r[7])
        : "l"(p));
}

__device__ __forceinline__ void stg_v8_cs(float* p, const float* r) {
    asm volatile(
        "st.global.cs.v8.f32 [%0], {%1,%2,%3,%4,%5,%6,%7,%8};"
        :: "l"(p),
           "f"(r[0]), "f"(r[1]), "f"(r[2]), "f"(r[3]),
           "f"(r[4]), "f"(r[5]), "f"(r[6]), "f"(r[7])
        : "memory");
}

__global__ __launch_bounds__(THREADS)
void normalizer_kernel(const float* __restrict__ adj,
                       float* __restrict__ out)
{
    const long long base = (long long)blockIdx.x * ROW_N;
    const int t = threadIdx.x;
    const long long off = base + (long long)t * 8;   // 32B-aligned per thread

    // One 256-bit load: this thread's 8 contiguous floats of the row.
    float v[8];
    ldg_v8_cs(adj + off, v);

    // Per-thread partial sum (tree)
    float s = ((v[0] + v[1]) + (v[2] + v[3])) + ((v[4] + v[5]) + (v[6] + v[7]));

    // Warp reduction
#pragma unroll
    for (int o = 16; o > 0; o >>= 1)
        s += __shfl_xor_sync(0xFFFFFFFFu, s, o);

    // Block reduction: one barrier, every thread folds the warp partials.
    __shared__ float warp_sums[NWARPS];
    if ((t & 31) == 0) warp_sums[t >> 5] = s;
    __syncthreads();

    float deg = 0.0f;
#pragma unroll
    for (int w = 0; w < NWARPS; w++)
        deg += warp_sums[w];

    float inv = 1.0f / deg;
    if (!isfinite(inv)) inv = 0.0f;

    // Scale and one 256-bit store.
#pragma unroll
    for (int i = 0; i < 8; i++)
        v[i] *= inv;
    stg_v8_cs(out + off, v);
}

extern "C" void kernel_launch(void* const* d_in, const int* in_sizes, int n_in,
                              void* d_out, int out_size)
{
    const float* adj = (const float*)d_in[0];
    float* out = (float*)d_out;

    const long long total = (long long)in_sizes[0];
    const long long rows  = total / ROW_N;   // 32768 for [2,8,2048,2048]

    normalizer_kernel<<<(unsigned)rows, THREADS>>>(adj, out);
}

// round 11
// speedup vs baseline: 1.0027x; 1.0027x over previous
#include <cuda_runtime.h>

// Row-normalize: out[row, :] = adj[row, :] * inv(sum(adj[row, :]))
// adj: [L*B*N, N] fp32, N = 2048. One CTA per row.
// sm_103a 256-bit global accesses: each thread does exactly ONE
// ld.global.v8.f32 (32 B) and ONE st.global.v8.f32 — minimal LSU
// wavefronts for the 512 MiB stream. Best measured: 73.4us kernel,
// 6545 GB/s (82.6% DRAM), vs 74.9us for all float4 variants.

static constexpr int ROW_N   = 2048;
static constexpr int THREADS = 256;          // 8 floats per thread = one v8
static constexpr int NWARPS  = THREADS / 32;

__device__ __forceinline__ void ldg_v8_cs(const float* p, float* r) {
    asm volatile(
        "ld.global.cs.v8.f32 {%0,%1,%2,%3,%4,%5,%6,%7}, [%8];"
        : "=f"(r[0]), "=f"(r[1]), "=f"(r[2]), "=f"(r[3]),
          "=f"(r[4]), "=f"(r[5]), "=f"(r[6]), "=f"(r[7])
        : "l"(p));
}

__device__ __forceinline__ void stg_v8_cs(float* p, const float* r) {
    asm volatile(
        "st.global.cs.v8.f32 [%0], {%1,%2,%3,%4,%5,%6,%7,%8};"
        :: "l"(p),
           "f"(r[0]), "f"(r[1]), "f"(r[2]), "f"(r[3]),
           "f"(r[4]), "f"(r[5]), "f"(r[6]), "f"(r[7])
        : "memory");
}

__global__ __launch_bounds__(THREADS)
void normalizer_kernel(const float* __restrict__ adj,
                       float* __restrict__ out)
{
    const long long base = (long long)blockIdx.x * ROW_N;
    const int t = threadIdx.x;
    const long long off = base + (long long)t * 8;   // 32B-aligned per thread

    // One 256-bit load: this thread's 8 contiguous floats of the row.
    float v[8];
    ldg_v8_cs(adj + off, v);

    // Per-thread partial sum (tree)
    float s = ((v[0] + v[1]) + (v[2] + v[3])) + ((v[4] + v[5]) + (v[6] + v[7]));

    // Warp reduction
#pragma unroll
    for (int o = 16; o > 0; o >>= 1)
        s += __shfl_xor_sync(0xFFFFFFFFu, s, o);

    // Block reduction: one barrier, every thread folds the warp partials.
    __shared__ float warp_sums[NWARPS];
    if ((t & 31) == 0) warp_sums[t >> 5] = s;
    __syncthreads();

    float deg = 0.0f;
#pragma unroll
    for (int w = 0; w < NWARPS; w++)
        deg += warp_sums[w];

    float inv = 1.0f / deg;
    if (!isfinite(inv)) inv = 0.0f;

    // Scale and one 256-bit store.
#pragma unroll
    for (int i = 0; i < 8; i++)
        v[i] *= inv;
    stg_v8_cs(out + off, v);
}

extern "C" void kernel_launch(void* const* d_in, const int* in_sizes, int n_in,
                              void* d_out, int out_size)
{
    const float* adj = (const float*)d_in[0];
    float* out = (float*)d_out;

    const long long total = (long long)in_sizes[0];
    const long long rows  = total / ROW_N;   // 32768 for [2,8,2048,2048]

    normalizer_kernel<<<(unsigned)rows, THREADS>>>(adj, out);
}

// round 13
// speedup vs baseline: 1.0231x; 1.0203x over previous
#include <cuda_runtime.h>

// Row-normalize: out[row, :] = adj[row, :] * inv(sum(adj[row, :]))
// adj: [L*B*N, N] fp32, N = 2048. One CTA per row.
//
// FINAL converged kernel. Single-pass (read 256 MiB once, write 256 MiB
// once), row register-resident, one 256-bit ld.global + one 256-bit
// st.global per thread. Session evidence: all structural variants
// (block/warp reductions, 0-2 barriers, 128b/256b, cache hints, occ
// 30-94%) land at 73.4-75.4us kernel / ~6.4 TB/s — the realized sm_103a
// streaming ceiling. This variant has the best mean and fewest LSU ops.

static constexpr int ROW_N   = 2048;
static constexpr int THREADS = 256;          // 8 floats per thread = one v8
static constexpr int NWARPS  = THREADS / 32;

__device__ __forceinline__ void ldg_v8_cs(const float* p, float* r) {
    asm volatile(
        "ld.global.cs.v8.f32 {%0,%1,%2,%3,%4,%5,%6,%7}, [%8];"
        : "=f"(r[0]), "=f"(r[1]), "=f"(r[2]), "=f"(r[3]),
          "=f"(r[4]), "=f"(r[5]), "=f"(r[6]), "=f"(r[7])
        : "l"(p));
}

__device__ __forceinline__ void stg_v8_cs(float* p, const float* r) {
    asm volatile(
        "st.global.cs.v8.f32 [%0], {%1,%2,%3,%4,%5,%6,%7,%8};"
        :: "l"(p),
           "f"(r[0]), "f"(r[1]), "f"(r[2]), "f"(r[3]),
           "f"(r[4]), "f"(r[5]), "f"(r[6]), "f"(r[7])
        : "memory");
}

__global__ __launch_bounds__(THREADS)
void normalizer_kernel(const float* __restrict__ adj,
                       float* __restrict__ out)
{
    const long long base = (long long)blockIdx.x * ROW_N;
    const int t = threadIdx.x;
    const long long off = base + (long long)t * 8;   // 32B-aligned per thread

    // One 256-bit load: this thread's 8 contiguous floats of the row.
    float v[8];
    ldg_v8_cs(adj + off, v);

    // Per-thread partial sum (tree)
    float s = ((v[0] + v[1]) + (v[2] + v[3])) + ((v[4] + v[5]) + (v[6] + v[7]));

    // Warp reduction
#pragma unroll
    for (int o = 16; o > 0; o >>= 1)
        s += __shfl_xor_sync(0xFFFFFFFFu, s, o);

    // Block reduction: one barrier, every thread folds the warp partials.
    __shared__ float warp_sums[NWARPS];
    if ((t & 31) == 0) warp_sums[t >> 5] = s;
    __syncthreads();

    float deg = 0.0f;
#pragma unroll
    for (int w = 0; w < NWARPS; w++)
        deg += warp_sums[w];

    float inv = 1.0f / deg;
    if (!isfinite(inv)) inv = 0.0f;

    // Scale and one 256-bit store.
#pragma unroll
    for (int i = 0; i < 8; i++)
        v[i] *= inv;
    stg_v8_cs(out + off, v);
}

extern "C" void kernel_launch(void* const* d_in, const int* in_sizes, int n_in,
                              void* d_out, int out_size)
{
    const float* adj = (const float*)d_in[0];
    float* out = (float*)d_out;

    const long long total = (long long)in_sizes[0];
    const long long rows  = total / ROW_N;   // 32768 for [2,8,2048,2048]

    normalizer_kernel<<<(unsigned)rows, THREADS>>>(adj, out);
}